// round 11
// baseline (speedup 1.0000x reference)
#include <cuda_runtime.h>
#include <math.h>

#define NN   512
#define CSd  384
#define CZd  128
#define Hd   12
#define Cd   16
#define PQd  4
#define PVd  8
#define DE   28
#define CATd 2017
#define MPROJ 1152
#define KSPLIT 8

typedef unsigned long long ull;

// ---------------- packed f32x2 helpers ----------------
__device__ __forceinline__ void ffma2(ull& acc, ull a, ull b) {
    asm("fma.rn.f32x2 %0, %1, %2, %0;" : "+l"(acc) : "l"(a), "l"(b));
}
__device__ __forceinline__ ull pk2(float x, float y) {
    ull r; asm("mov.b64 %0, {%1,%2};" : "=l"(r) : "f"(x), "f"(y)); return r;
}
__device__ __forceinline__ void upk2(ull v, float& x, float& y) {
    asm("mov.b64 {%0,%1}, %2;" : "=f"(x), "=f"(y) : "l"(v));
}

// ---------------- device scratch ----------------
__device__ float g_P[MPROJ * NN];
__device__ float g_qe[Hd * DE * NN];
__device__ float g_ke[Hd * DE * NN];
__device__ float g_qn[Hd * NN];
__device__ float g_kn[Hd * NN];
__device__ float g_V[Hd * 48 * NN];          // per-head value table: [h][48 rows][j]
__device__ float g_Lqk[Hd * NN * NN];        // qk - dist partial [h][i][j]
__device__ float g_A[NN * Hd * NN];          // probs [i][h][j]
__device__ float g_o3g[288 * NN];            // global-frame o3 [rr][i]
__device__ float g_cat[CATd * NN];
__device__ float g_part[KSPLIT * CSd * NN];

// ---------------- projection GEMM with fused weight concat ----------------
__global__ __launch_bounds__(256) void proj_gemm(const float* __restrict__ s,
                                                 const float* __restrict__ Wq,
                                                 const float* __restrict__ Wk,
                                                 const float* __restrict__ Wv,
                                                 const float* __restrict__ Wqp,
                                                 const float* __restrict__ Wkp,
                                                 const float* __restrict__ Wvp) {
    __shared__ float As[16][64];
    __shared__ ull   Bs2[16][64];

    const int nb = blockIdx.x, mb = blockIdx.y;
    const int tid = threadIdx.x;
    const int ty = tid >> 4, tx = tid & 15;

    const float* rowp[4];
#pragma unroll
    for (int l = 0; l < 4; ++l) {
        int e = tid + l * 256;
        int r = mb * 64 + (e >> 4);
        const float* p;
        if      (r < 192) p = Wq  + (size_t)r * CSd;
        else if (r < 384) p = Wk  + (size_t)(r - 192) * CSd;
        else if (r < 576) p = Wv  + (size_t)(r - 384) * CSd;
        else if (r < 720) p = Wqp + (size_t)(r - 576) * CSd;
        else if (r < 864) p = Wkp + (size_t)(r - 720) * CSd;
        else              p = Wvp + (size_t)(r - 864) * CSd;
        rowp[l] = p;
    }

    ull acc2[2][4];
#pragma unroll
    for (int u = 0; u < 2; ++u)
#pragma unroll
        for (int v = 0; v < 4; ++v) acc2[u][v] = 0ull;

    for (int kk = 0; kk < CSd; kk += 16) {
#pragma unroll
        for (int l = 0; l < 4; ++l) {
            int e = tid + l * 256;
            As[e & 15][e >> 4] = rowp[l][kk + (e & 15)];
        }
#pragma unroll
        for (int l = 0; l < 4; ++l) {
            int e = tid + l * 256;
            int k = e >> 6, n = e & 63;
            float v = s[(size_t)(kk + k) * NN + nb * 64 + n];
            Bs2[k][n] = pk2(v, v);
        }
        __syncthreads();
#pragma unroll
        for (int k = 0; k < 16; ++k) {
            const ull* a2 = (const ull*)&As[k][ty * 4];
            ull a0 = a2[0], a1 = a2[1];
            ull b0 = Bs2[k][tx * 4], b1 = Bs2[k][tx * 4 + 1];
            ull b2 = Bs2[k][tx * 4 + 2], b3 = Bs2[k][tx * 4 + 3];
            ffma2(acc2[0][0], a0, b0); ffma2(acc2[0][1], a0, b1);
            ffma2(acc2[0][2], a0, b2); ffma2(acc2[0][3], a0, b3);
            ffma2(acc2[1][0], a1, b0); ffma2(acc2[1][1], a1, b1);
            ffma2(acc2[1][2], a1, b2); ffma2(acc2[1][3], a1, b3);
        }
        __syncthreads();
    }
#pragma unroll
    for (int u = 0; u < 2; ++u)
#pragma unroll
        for (int v = 0; v < 4; ++v) {
            float lo, hi;
            upk2(acc2[u][v], lo, hi);
            g_P[(size_t)(mb * 64 + ty * 4 + u * 2    ) * NN + nb * 64 + tx * 4 + v] = lo;
            g_P[(size_t)(mb * 64 + ty * 4 + u * 2 + 1) * NN + nb * 64 + tx * 4 + v] = hi;
        }
}

// ---------------- prep: parallel over (h, i) ----------------
__global__ __launch_bounds__(128) void prep_kernel(const float* __restrict__ t_r,
                                                   const float* __restrict__ t_t,
                                                   const float* __restrict__ gamma) {
    int idx = blockIdx.x * 128 + threadIdx.x;
    int h = idx >> 9, i = idx & 511;
    const float w_c = 0.23570226039551584f;
    float R[9], T[3];
#pragma unroll
    for (int r = 0; r < 9; ++r) R[r] = t_r[i * 9 + r];
#pragma unroll
    for (int c = 0; c < 3; ++c) T[c] = t_t[i * 3 + c];

    float x = gamma[h];
    float sp = (x > 20.f) ? x : log1pf(expf(x));
    float g = sp * w_c * 0.5f;

#pragma unroll
    for (int c = 0; c < Cd; ++c) {
        g_qe[(h * DE + c) * NN + i] = g_P[(      c * Hd + h) * NN + i] * 0.25f;
        g_ke[(h * DE + c) * NN + i] = g_P[(192 + c * Hd + h) * NN + i];
    }
    float qn = 0.f, kn = 0.f;
#pragma unroll
    for (int p = 0; p < PQd; ++p) {
        float q0 = g_P[(576 +  0 + h * 4 + p) * NN + i];
        float q1 = g_P[(576 + 48 + h * 4 + p) * NN + i];
        float q2 = g_P[(576 + 96 + h * 4 + p) * NN + i];
        float k0 = g_P[(720 +  0 + h * 4 + p) * NN + i];
        float k1 = g_P[(720 + 48 + h * 4 + p) * NN + i];
        float k2 = g_P[(720 + 96 + h * 4 + p) * NN + i];
#pragma unroll
        for (int co = 0; co < 3; ++co) {
            float qg = R[co * 3] * q0 + R[co * 3 + 1] * q1 + R[co * 3 + 2] * q2 + T[co];
            float kg = R[co * 3] * k0 + R[co * 3 + 1] * k1 + R[co * 3 + 2] * k2 + T[co];
            g_qe[(h * DE + 16 + co * 4 + p) * NN + i] = 2.f * g * qg;
            g_ke[(h * DE + 16 + co * 4 + p) * NN + i] = kg;
            qn += qg * qg;
            kn += kg * kg;
        }
    }
    g_qn[h * NN + i] = g * qn;
    g_kn[h * NN + i] = g * kn;

    // V table rows 0..15: o2 channel values
#pragma unroll
    for (int c = 0; c < Cd; ++c)
        g_V[(size_t)(h * 48 + c) * NN + i] = g_P[(384 + c * Hd + h) * NN + i];

    // V table rows 16..39: global-frame v points
#pragma unroll
    for (int p = 0; p < PVd; ++p) {
        float v0 = g_P[(864 +   0 + h * 8 + p) * NN + i];
        float v1 = g_P[(864 +  96 + h * 8 + p) * NN + i];
        float v2 = g_P[(864 + 192 + h * 8 + p) * NN + i];
#pragma unroll
        for (int co = 0; co < 3; ++co)
            g_V[(size_t)(h * 48 + 16 + co * 8 + p) * NN + i] =
                R[co * 3] * v0 + R[co * 3 + 1] * v1 + R[co * 3 + 2] * v2 + T[co];
    }
    // pad rows 40..47
#pragma unroll
    for (int r = 40; r < 48; ++r)
        g_V[(size_t)(h * 48 + r) * NN + i] = 0.f;
}

// ---------------- qk batched GEMM: Lqk[h] = qe[h]^T . ke[h] ----------------
__global__ __launch_bounds__(256) void qk_gemm() {
    __shared__ float As[32][64];
    __shared__ ull   Bs2[32][64];
    const int h = blockIdx.z, mb = blockIdx.y, nb = blockIdx.x;
    const float* Aq = g_qe + (size_t)h * DE * NN;
    const float* Bk = g_ke + (size_t)h * DE * NN;
    int tid = threadIdx.x, ty = tid >> 4, tx = tid & 15;

#pragma unroll
    for (int l = 0; l < 8; ++l) {
        int e = tid + l * 256, k = e >> 6, m = e & 63;
        if (k < DE) {
            As[k][m] = Aq[k * NN + mb * 64 + m];
            float v = Bk[k * NN + nb * 64 + m];
            Bs2[k][m] = pk2(v, v);
        }
    }
    __syncthreads();

    ull acc2[2][4];
#pragma unroll
    for (int u = 0; u < 2; ++u)
#pragma unroll
        for (int v = 0; v < 4; ++v) acc2[u][v] = 0ull;

#pragma unroll
    for (int k = 0; k < DE; ++k) {
        const ull* a2 = (const ull*)&As[k][ty * 4];
        ull a0 = a2[0], a1 = a2[1];
        ull b0 = Bs2[k][tx * 4], b1 = Bs2[k][tx * 4 + 1];
        ull b2 = Bs2[k][tx * 4 + 2], b3 = Bs2[k][tx * 4 + 3];
        ffma2(acc2[0][0], a0, b0); ffma2(acc2[0][1], a0, b1);
        ffma2(acc2[0][2], a0, b2); ffma2(acc2[0][3], a0, b3);
        ffma2(acc2[1][0], a1, b0); ffma2(acc2[1][1], a1, b1);
        ffma2(acc2[1][2], a1, b2); ffma2(acc2[1][3], a1, b3);
    }
    float* C = g_Lqk + (size_t)h * NN * NN;
#pragma unroll
    for (int u = 0; u < 2; ++u)
#pragma unroll
        for (int v = 0; v < 4; ++v) {
            float lo, hi;
            upk2(acc2[u][v], lo, hi);
            C[(size_t)(mb * 64 + ty * 4 + u * 2    ) * NN + nb * 64 + tx * 4 + v] = lo;
            C[(size_t)(mb * 64 + ty * 4 + u * 2 + 1) * NN + nb * 64 + tx * 4 + v] = hi;
        }
}

// ======== fused bias + logits + softmax: ONE query row per block ========
__global__ __launch_bounds__(256, 2) void bias_softmax_kernel(const float* __restrict__ Z,
                                                              const float* __restrict__ Wb) {
    __shared__ ull   W2s[CZd * Hd];
    __shared__ ull   part[Hd * 256];
    __shared__ float redM[Hd][4];
    __shared__ float redS[Hd][4];
    __shared__ float qns[Hd];

    const int tid = threadIdx.x;
    const int i = blockIdx.x;
    const int j4 = tid & 127;
    const int ch = tid >> 7;
    const int warpIn = tid >> 5;
    const int lane = tid & 31;
    const float w_l = 0.5773502691896258f;

    for (int e = tid; e < CZd * Hd; e += 256) {
        int c = e / 12, h = e % 12;
        float w = Wb[h * CZd + c];
        W2s[e] = pk2(w, w);
    }
    if (tid < 12) qns[tid] = g_qn[tid * NN + i];
    __syncthreads();

    ull acc[Hd][2];
#pragma unroll
    for (int h = 0; h < Hd; ++h) { acc[h][0] = 0ull; acc[h][1] = 0ull; }

    const float4* z4 = (const float4*)Z + (size_t)i * 128 + j4;
    const int c0 = ch * 64;
    for (int cb = 0; cb < 64; cb += 8) {
        float4 zv[8];
#pragma unroll
        for (int u = 0; u < 8; ++u)
            zv[u] = __ldg(&z4[(size_t)(c0 + cb + u) * 65536]);
#pragma unroll
        for (int u = 0; u < 8; ++u) {
            ull zx = pk2(zv[u].x, zv[u].y), zy = pk2(zv[u].z, zv[u].w);
#pragma unroll
            for (int h = 0; h < Hd; ++h) {
                ull w2 = W2s[(c0 + cb + u) * 12 + h];
                ffma2(acc[h][0], w2, zx);
                ffma2(acc[h][1], w2, zy);
            }
        }
    }

    if (ch == 1) {
#pragma unroll
        for (int h = 0; h < Hd; ++h) {
            part[h * 256 + j4]       = acc[h][0];
            part[h * 256 + 128 + j4] = acc[h][1];
        }
    }
    __syncthreads();

    if (ch == 0) {
#pragma unroll
        for (int h = 0; h < Hd; ++h) {
            float a0, a1, b0, b1;
            upk2(acc[h][0], a0, a1);
            upk2(part[h * 256 + j4], b0, b1);
            float c0f = a0 + b0, c1f = a1 + b1;
            upk2(acc[h][1], a0, a1);
            upk2(part[h * 256 + 128 + j4], b0, b1);
            float c2f = a0 + b0, c3f = a1 + b1;

            float4 qk = __ldg((const float4*)g_Lqk + (size_t)h * 65536 + (size_t)i * 128 + j4);
            float4 kn = __ldg((const float4*)g_kn + h * 128 + j4);
            float qn = qns[h];
            c0f = w_l * (c0f + qk.x - qn - kn.x);
            c1f = w_l * (c1f + qk.y - qn - kn.y);
            c2f = w_l * (c2f + qk.z - qn - kn.z);
            c3f = w_l * (c3f + qk.w - qn - kn.w);
            acc[h][0] = pk2(c0f, c1f);
            acc[h][1] = pk2(c2f, c3f);
            float m = fmaxf(fmaxf(c0f, c1f), fmaxf(c2f, c3f));
#pragma unroll
            for (int o = 16; o; o >>= 1) m = fmaxf(m, __shfl_xor_sync(0xffffffffu, m, o));
            if (lane == 0) redM[h][warpIn] = m;
        }
    }
    __syncthreads();

    if (ch == 0) {
#pragma unroll
        for (int h = 0; h < Hd; ++h) {
            const float* r = redM[h];
            float m = fmaxf(fmaxf(r[0], r[1]), fmaxf(r[2], r[3]));
            float a0, a1, a2, a3;
            upk2(acc[h][0], a0, a1);
            upk2(acc[h][1], a2, a3);
            a0 = __expf(a0 - m); a1 = __expf(a1 - m);
            a2 = __expf(a2 - m); a3 = __expf(a3 - m);
            acc[h][0] = pk2(a0, a1);
            acc[h][1] = pk2(a2, a3);
            float s = (a0 + a1) + (a2 + a3);
#pragma unroll
            for (int o = 16; o; o >>= 1) s += __shfl_xor_sync(0xffffffffu, s, o);
            if (lane == 0) redS[h][warpIn] = s;
        }
    }
    __syncthreads();

    if (ch == 0) {
        float4* A4 = (float4*)g_A;
#pragma unroll
        for (int h = 0; h < Hd; ++h) {
            const float* r = redS[h];
            float inv = 1.f / ((r[0] + r[1]) + (r[2] + r[3]));
            float a0, a1, a2, a3;
            upk2(acc[h][0], a0, a1);
            upk2(acc[h][1], a2, a3);
            float4 p;
            p.x = a0 * inv; p.y = a1 * inv; p.z = a2 * inv; p.w = a3 * inv;
            A4[(size_t)i * 1536 + h * 128 + j4] = p;
        }
    }
}

// ---------------- o1: per (i, c-half), 2 c's per warp, staged z ----------------
__global__ __launch_bounds__(256) void o1k(const float* __restrict__ Z) {
    __shared__ ull Ps[Hd * 256];
    const int i = blockIdx.x;
    const int ks = blockIdx.y;
    const int tid = threadIdx.x;
    const int warp = tid >> 5, lane = tid & 31;

    {
        const ull* src = (const ull*)(g_A + (size_t)i * Hd * NN);
        for (int e = tid; e < Hd * 256; e += 256) Ps[e] = src[e];
    }
    __syncthreads();
    const ulonglong2* Ps2 = (const ulonglong2*)Ps;

#pragma unroll
    for (int cp = 0; cp < 4; ++cp) {
        const int c = ks * 64 + cp * 16 + warp * 2;
        const ulonglong2* zc0 = (const ulonglong2*)(Z + ((size_t)c * NN + i) * NN);
        const ulonglong2* zc1 = (const ulonglong2*)(Z + ((size_t)(c + 1) * NN + i) * NN);
        ulonglong2 z0[4], z1[4];
#pragma unroll
        for (int q = 0; q < 4; ++q) {
            z0[q] = __ldg(&zc0[lane + 32 * q]);
            z1[q] = __ldg(&zc1[lane + 32 * q]);
        }
        ull acc[Hd][2];
#pragma unroll
        for (int h = 0; h < Hd; ++h) { acc[h][0] = 0ull; acc[h][1] = 0ull; }
#pragma unroll
        for (int q = 0; q < 4; ++q) {
#pragma unroll
            for (int h = 0; h < Hd; ++h) {
                ulonglong2 pp = Ps2[h * 128 + lane + 32 * q];
                ffma2(acc[h][0], pp.x, z0[q].x);
                ffma2(acc[h][0], pp.y, z0[q].y);
                ffma2(acc[h][1], pp.x, z1[q].x);
                ffma2(acc[h][1], pp.y, z1[q].y);
            }
        }
#pragma unroll
        for (int h = 0; h < Hd; ++h) {
#pragma unroll
            for (int cc = 0; cc < 2; ++cc) {
                float lo, hi;
                upk2(acc[h][cc], lo, hi);
                float s = lo + hi;
#pragma unroll
                for (int o = 16; o; o >>= 1) s += __shfl_xor_sync(0xffffffffu, s, o);
                if (lane == 0) g_cat[(size_t)((c + cc) * Hd + h) * NN + i] = s;
            }
        }
    }
}

// ======== o2/o3 as per-head GEMM: O[48 r, 512 i] = V[48, 512 j] @ A_h[512 i, 512 j]^T ========
// grid (8 itile, 12 h), block 256 = (tx 16 -> 4 i each, ty 16 -> 3 rows each)
__global__ __launch_bounds__(256) void o23_gemm() {
    __shared__ float Vs[16][48];
    __shared__ float As[16][64];
    const int it = blockIdx.x, h = blockIdx.y;
    const int tid = threadIdx.x;
    const int tx = tid & 15, ty = tid >> 4;

    float acc[3][4];
#pragma unroll
    for (int u = 0; u < 3; ++u)
#pragma unroll
        for (int v = 0; v < 4; ++v) acc[u][v] = 0.f;

    const float* Vh = g_V + (size_t)h * 48 * NN;

    for (int kk = 0; kk < NN; kk += 16) {
#pragma unroll
        for (int l = 0; l < 3; ++l) {
            int e = tid + l * 256;
            int m = e >> 4, k = e & 15;
            Vs[k][m] = Vh[(size_t)m * NN + kk + k];
        }
#pragma unroll
        for (int l = 0; l < 4; ++l) {
            int e = tid + l * 256;
            int n = e >> 4, k = e & 15;
            As[k][n] = g_A[(size_t)(it * 64 + n) * (Hd * NN) + h * NN + kk + k];
        }
        __syncthreads();
#pragma unroll
        for (int k = 0; k < 16; ++k) {
            float a0 = Vs[k][ty * 3], a1 = Vs[k][ty * 3 + 1], a2 = Vs[k][ty * 3 + 2];
            float4 b = *(const float4*)&As[k][tx * 4];
            acc[0][0] += a0 * b.x; acc[0][1] += a0 * b.y; acc[0][2] += a0 * b.z; acc[0][3] += a0 * b.w;
            acc[1][0] += a1 * b.x; acc[1][1] += a1 * b.y; acc[1][2] += a1 * b.z; acc[1][3] += a1 * b.w;
            acc[2][0] += a2 * b.x; acc[2][1] += a2 * b.y; acc[2][2] += a2 * b.z; acc[2][3] += a2 * b.w;
        }
        __syncthreads();
    }

#pragma unroll
    for (int u = 0; u < 3; ++u) {
        int m = ty * 3 + u;
        if (m >= 40) continue;
#pragma unroll
        for (int v = 0; v < 4; ++v) {
            int i = it * 64 + tx * 4 + v;
            if (m < 16)
                g_cat[(size_t)(1536 + m * Hd + h) * NN + i] = acc[u][v];
            else {
                int d = m - 16;
                int rr = (d >> 3) * 96 + h * 8 + (d & 7);
                g_o3g[(size_t)rr * NN + i] = acc[u][v];
            }
        }
    }
}

// ---------------- o3 inverse transform + norm (warp per i) ----------------
__global__ void o3fix2(const float* __restrict__ t_r, const float* __restrict__ t_t) {
    int warp = threadIdx.x >> 5, lane = threadIdx.x & 31;
    int i = blockIdx.x * 8 + warp;
    float R[9], T[3];
#pragma unroll
    for (int r = 0; r < 9; ++r) R[r] = t_r[i * 9 + r];
#pragma unroll
    for (int c = 0; c < 3; ++c) T[c] = t_t[i * 3 + c];

    float nrm = 0.f;
    for (int hp = lane; hp < 96; hp += 32) {
        float a0 = g_o3g[(size_t)(0 * 96 + hp) * NN + i] - T[0];
        float a1 = g_o3g[(size_t)(1 * 96 + hp) * NN + i] - T[1];
        float a2 = g_o3g[(size_t)(2 * 96 + hp) * NN + i] - T[2];
#pragma unroll
        for (int co = 0; co < 3; ++co) {
            float v = R[co] * a0 + R[3 + co] * a1 + R[6 + co] * a2;
            g_cat[(size_t)(1728 + co * 96 + hp) * NN + i] = v;
            nrm += v * v;
        }
    }
#pragma unroll
    for (int o = 16; o; o >>= 1) nrm += __shfl_xor_sync(0xffffffffu, nrm, o);
    if (lane == 0) g_cat[(size_t)2016 * NN + i] = sqrtf(nrm);
}

// ======== final GEMM: 128x128 tiles, split-K, f32x2 ========
// grid (nb 4, mb 3, zb 8), block 256 = (tx 16 -> 8 n, ty 16 -> 8 m = 4 pairs)
__global__ __launch_bounds__(256) void gemm128(const float* __restrict__ A,
                                               const float* __restrict__ B,
                                               float* __restrict__ C,
                                               int M, int Nc, int K) {
    __shared__ float As[16][128];
    __shared__ ull   Bs2[16][128];

    const int nb = blockIdx.x, mb = blockIdx.y, zb = blockIdx.z;
    const int Kc = (K + gridDim.z - 1) / gridDim.z;
    const int k0 = zb * Kc;
    const int kend = min(K, k0 + Kc);

    const int tid = threadIdx.x;
    const int tx = tid & 15, ty = tid >> 4;

    ull acc2[4][8];
#pragma unroll
    for (int u = 0; u < 4; ++u)
#pragma unroll
        for (int v = 0; v < 8; ++v) acc2[u][v] = 0ull;

    for (int kk = k0; kk < kend; kk += 16) {
#pragma unroll
        for (int l = 0; l < 8; ++l) {
            int e = tid + l * 256;
            int m = e >> 4, k = e & 15;
            As[k][m] = (kk + k < kend) ? A[(size_t)(mb * 128 + m) * K + kk + k] : 0.f;
        }
#pragma unroll
        for (int l = 0; l < 8; ++l) {
            int e = tid + l * 256;
            int k = e >> 7, n = e & 127;
            float v = (kk + k < kend) ? B[(size_t)(kk + k) * Nc + nb * 128 + n] : 0.f;
            Bs2[k][n] = pk2(v, v);
        }
        __syncthreads();
#pragma unroll
        for (int k = 0; k < 16; ++k) {
            const ull* a2 = (const ull*)&As[k][ty * 8];
            ull a0 = a2[0], a1 = a2[1], a3 = a2[2], a4 = a2[3];
            const ull* bp = &Bs2[k][tx * 8];
#pragma unroll
            for (int v = 0; v < 8; ++v) {
                ull bv = bp[v];
                ffma2(acc2[0][v], a0, bv);
                ffma2(acc2[1][v], a1, bv);
                ffma2(acc2[2][v], a3, bv);
                ffma2(acc2[3][v], a4, bv);
            }
        }
        __syncthreads();
    }
    float* Cz = C + (size_t)zb * M * Nc;
#pragma unroll
    for (int u = 0; u < 4; ++u)
#pragma unroll
        for (int v = 0; v < 8; ++v) {
            float lo, hi;
            upk2(acc2[u][v], lo, hi);
            Cz[(size_t)(mb * 128 + ty * 8 + u * 2    ) * Nc + nb * 128 + tx * 8 + v] = lo;
            Cz[(size_t)(mb * 128 + ty * 8 + u * 2 + 1) * Nc + nb * 128 + tx * 8 + v] = hi;
        }
}

// ---------------- final reduce ----------------
__global__ void reduce_out(const float* __restrict__ bs, float* __restrict__ out) {
    int idx = blockIdx.x * 256 + threadIdx.x;
    if (idx >= CSd * NN) return;
    int o = idx >> 9;
    float v = bs[o];
#pragma unroll
    for (int zk = 0; zk < KSPLIT; ++zk) v += g_part[(size_t)zk * CSd * NN + idx];
    out[idx] = v;
}

// ---------------- launcher (serial) ----------------
extern "C" void kernel_launch(void* const* d_in, const int* in_sizes, int n_in,
                              void* d_out, int out_size) {
    const float* s    = (const float*)d_in[0];
    const float* z    = (const float*)d_in[1];
    const float* t_r  = (const float*)d_in[2];
    const float* t_t  = (const float*)d_in[3];
    const float* Wq   = (const float*)d_in[4];
    const float* Wk   = (const float*)d_in[5];
    const float* Wv   = (const float*)d_in[6];
    const float* Wqp  = (const float*)d_in[7];
    const float* Wkp  = (const float*)d_in[8];
    const float* Wvp  = (const float*)d_in[9];
    const float* Wb   = (const float*)d_in[10];
    const float* gam  = (const float*)d_in[11];
    const float* Ws   = (const float*)d_in[12];
    const float* bs   = (const float*)d_in[13];
    float* out = (float*)d_out;

    float *pCat, *pPart;
    cudaGetSymbolAddress((void**)&pCat,  g_cat);
    cudaGetSymbolAddress((void**)&pPart, g_part);

    proj_gemm<<<dim3(NN / 64, MPROJ / 64), 256>>>(s, Wq, Wk, Wv, Wqp, Wkp, Wvp);
    prep_kernel<<<Hd * NN / 128, 128>>>(t_r, t_t, gam);
    qk_gemm<<<dim3(NN / 64, NN / 64, Hd), 256>>>();
    bias_softmax_kernel<<<NN, 256>>>(z, Wb);
    o1k<<<dim3(NN, 2), 256>>>(z);
    o23_gemm<<<dim3(8, Hd), 256>>>();
    o3fix2<<<NN / 8, 256>>>(t_r, t_t);
    gemm128<<<dim3(4, 3, KSPLIT), 256>>>(Ws, pCat, pPart, CSd, NN, CATd);
    reduce_out<<<(CSd * NN + 255) / 256, 256>>>(bs, out);
}

// round 12
// speedup vs baseline: 1.1578x; 1.1578x over previous
#include <cuda_runtime.h>
#include <math.h>

#define NN   512
#define CSd  384
#define CZd  128
#define Hd   12
#define Cd   16
#define PQd  4
#define PVd  8
#define DE   28
#define CATd 2017
#define MPROJ 1152
#define KSPLIT 8

typedef unsigned long long ull;

// ---------------- packed f32x2 helpers ----------------
__device__ __forceinline__ void ffma2(ull& acc, ull a, ull b) {
    asm("fma.rn.f32x2 %0, %1, %2, %0;" : "+l"(acc) : "l"(a), "l"(b));
}
__device__ __forceinline__ ull pk2(float x, float y) {
    ull r; asm("mov.b64 %0, {%1,%2};" : "=l"(r) : "f"(x), "f"(y)); return r;
}
__device__ __forceinline__ void upk2(ull v, float& x, float& y) {
    asm("mov.b64 {%0,%1}, %2;" : "=f"(x), "=f"(y) : "l"(v));
}

// ---------------- device scratch ----------------
__device__ float g_P[MPROJ * NN];
__device__ float g_qe[Hd * DE * NN];
__device__ float g_ke[Hd * DE * NN];
__device__ float g_qn[Hd * NN];
__device__ float g_kn[Hd * NN];
__device__ float g_V[Hd * 48 * NN];          // per-head value table: [h][48 rows][j]
__device__ float g_Lqk[Hd * NN * NN];        // qk - dist partial [h][i][j]
__device__ float g_A[NN * Hd * NN];          // probs [i][h][j]
__device__ float g_o3g[288 * NN];            // global-frame o3 [rr][i]
__device__ float g_cat[CATd * NN];
__device__ float g_part[KSPLIT * CSd * NN];

// ---------------- projection GEMM with fused weight concat ----------------
__global__ __launch_bounds__(256) void proj_gemm(const float* __restrict__ s,
                                                 const float* __restrict__ Wq,
                                                 const float* __restrict__ Wk,
                                                 const float* __restrict__ Wv,
                                                 const float* __restrict__ Wqp,
                                                 const float* __restrict__ Wkp,
                                                 const float* __restrict__ Wvp) {
    __shared__ float As[16][64];
    __shared__ ull   Bs2[16][64];

    const int nb = blockIdx.x, mb = blockIdx.y;
    const int tid = threadIdx.x;
    const int ty = tid >> 4, tx = tid & 15;

    const float* rowp[4];
#pragma unroll
    for (int l = 0; l < 4; ++l) {
        int e = tid + l * 256;
        int r = mb * 64 + (e >> 4);
        const float* p;
        if      (r < 192) p = Wq  + (size_t)r * CSd;
        else if (r < 384) p = Wk  + (size_t)(r - 192) * CSd;
        else if (r < 576) p = Wv  + (size_t)(r - 384) * CSd;
        else if (r < 720) p = Wqp + (size_t)(r - 576) * CSd;
        else if (r < 864) p = Wkp + (size_t)(r - 720) * CSd;
        else              p = Wvp + (size_t)(r - 864) * CSd;
        rowp[l] = p;
    }

    ull acc2[2][4];
#pragma unroll
    for (int u = 0; u < 2; ++u)
#pragma unroll
        for (int v = 0; v < 4; ++v) acc2[u][v] = 0ull;

    for (int kk = 0; kk < CSd; kk += 16) {
#pragma unroll
        for (int l = 0; l < 4; ++l) {
            int e = tid + l * 256;
            As[e & 15][e >> 4] = rowp[l][kk + (e & 15)];
        }
#pragma unroll
        for (int l = 0; l < 4; ++l) {
            int e = tid + l * 256;
            int k = e >> 6, n = e & 63;
            float v = s[(size_t)(kk + k) * NN + nb * 64 + n];
            Bs2[k][n] = pk2(v, v);
        }
        __syncthreads();
#pragma unroll
        for (int k = 0; k < 16; ++k) {
            const ull* a2 = (const ull*)&As[k][ty * 4];
            ull a0 = a2[0], a1 = a2[1];
            ull b0 = Bs2[k][tx * 4], b1 = Bs2[k][tx * 4 + 1];
            ull b2 = Bs2[k][tx * 4 + 2], b3 = Bs2[k][tx * 4 + 3];
            ffma2(acc2[0][0], a0, b0); ffma2(acc2[0][1], a0, b1);
            ffma2(acc2[0][2], a0, b2); ffma2(acc2[0][3], a0, b3);
            ffma2(acc2[1][0], a1, b0); ffma2(acc2[1][1], a1, b1);
            ffma2(acc2[1][2], a1, b2); ffma2(acc2[1][3], a1, b3);
        }
        __syncthreads();
    }
#pragma unroll
    for (int u = 0; u < 2; ++u)
#pragma unroll
        for (int v = 0; v < 4; ++v) {
            float lo, hi;
            upk2(acc2[u][v], lo, hi);
            g_P[(size_t)(mb * 64 + ty * 4 + u * 2    ) * NN + nb * 64 + tx * 4 + v] = lo;
            g_P[(size_t)(mb * 64 + ty * 4 + u * 2 + 1) * NN + nb * 64 + tx * 4 + v] = hi;
        }
}

// ---------------- prep: parallel over (h, i) ----------------
__global__ __launch_bounds__(128) void prep_kernel(const float* __restrict__ t_r,
                                                   const float* __restrict__ t_t,
                                                   const float* __restrict__ gamma) {
    int idx = blockIdx.x * 128 + threadIdx.x;
    int h = idx >> 9, i = idx & 511;
    const float w_c = 0.23570226039551584f;
    float R[9], T[3];
#pragma unroll
    for (int r = 0; r < 9; ++r) R[r] = t_r[i * 9 + r];
#pragma unroll
    for (int c = 0; c < 3; ++c) T[c] = t_t[i * 3 + c];

    float x = gamma[h];
    float sp = (x > 20.f) ? x : log1pf(expf(x));
    float g = sp * w_c * 0.5f;

#pragma unroll
    for (int c = 0; c < Cd; ++c) {
        g_qe[(h * DE + c) * NN + i] = g_P[(      c * Hd + h) * NN + i] * 0.25f;
        g_ke[(h * DE + c) * NN + i] = g_P[(192 + c * Hd + h) * NN + i];
    }
    float qn = 0.f, kn = 0.f;
#pragma unroll
    for (int p = 0; p < PQd; ++p) {
        float q0 = g_P[(576 +  0 + h * 4 + p) * NN + i];
        float q1 = g_P[(576 + 48 + h * 4 + p) * NN + i];
        float q2 = g_P[(576 + 96 + h * 4 + p) * NN + i];
        float k0 = g_P[(720 +  0 + h * 4 + p) * NN + i];
        float k1 = g_P[(720 + 48 + h * 4 + p) * NN + i];
        float k2 = g_P[(720 + 96 + h * 4 + p) * NN + i];
#pragma unroll
        for (int co = 0; co < 3; ++co) {
            float qg = R[co * 3] * q0 + R[co * 3 + 1] * q1 + R[co * 3 + 2] * q2 + T[co];
            float kg = R[co * 3] * k0 + R[co * 3 + 1] * k1 + R[co * 3 + 2] * k2 + T[co];
            g_qe[(h * DE + 16 + co * 4 + p) * NN + i] = 2.f * g * qg;
            g_ke[(h * DE + 16 + co * 4 + p) * NN + i] = kg;
            qn += qg * qg;
            kn += kg * kg;
        }
    }
    g_qn[h * NN + i] = g * qn;
    g_kn[h * NN + i] = g * kn;

#pragma unroll
    for (int c = 0; c < Cd; ++c)
        g_V[(size_t)(h * 48 + c) * NN + i] = g_P[(384 + c * Hd + h) * NN + i];

#pragma unroll
    for (int p = 0; p < PVd; ++p) {
        float v0 = g_P[(864 +   0 + h * 8 + p) * NN + i];
        float v1 = g_P[(864 +  96 + h * 8 + p) * NN + i];
        float v2 = g_P[(864 + 192 + h * 8 + p) * NN + i];
#pragma unroll
        for (int co = 0; co < 3; ++co)
            g_V[(size_t)(h * 48 + 16 + co * 8 + p) * NN + i] =
                R[co * 3] * v0 + R[co * 3 + 1] * v1 + R[co * 3 + 2] * v2 + T[co];
    }
#pragma unroll
    for (int r = 40; r < 48; ++r)
        g_V[(size_t)(h * 48 + r) * NN + i] = 0.f;
}

// ---------------- qk batched GEMM: Lqk[h] = qe[h]^T . ke[h] ----------------
__global__ __launch_bounds__(256) void qk_gemm() {
    __shared__ float As[32][64];
    __shared__ ull   Bs2[32][64];
    const int h = blockIdx.z, mb = blockIdx.y, nb = blockIdx.x;
    const float* Aq = g_qe + (size_t)h * DE * NN;
    const float* Bk = g_ke + (size_t)h * DE * NN;
    int tid = threadIdx.x, ty = tid >> 4, tx = tid & 15;

#pragma unroll
    for (int l = 0; l < 8; ++l) {
        int e = tid + l * 256, k = e >> 6, m = e & 63;
        if (k < DE) {
            As[k][m] = Aq[k * NN + mb * 64 + m];
            float v = Bk[k * NN + nb * 64 + m];
            Bs2[k][m] = pk2(v, v);
        }
    }
    __syncthreads();

    ull acc2[2][4];
#pragma unroll
    for (int u = 0; u < 2; ++u)
#pragma unroll
        for (int v = 0; v < 4; ++v) acc2[u][v] = 0ull;

#pragma unroll
    for (int k = 0; k < DE; ++k) {
        const ull* a2 = (const ull*)&As[k][ty * 4];
        ull a0 = a2[0], a1 = a2[1];
        ull b0 = Bs2[k][tx * 4], b1 = Bs2[k][tx * 4 + 1];
        ull b2 = Bs2[k][tx * 4 + 2], b3 = Bs2[k][tx * 4 + 3];
        ffma2(acc2[0][0], a0, b0); ffma2(acc2[0][1], a0, b1);
        ffma2(acc2[0][2], a0, b2); ffma2(acc2[0][3], a0, b3);
        ffma2(acc2[1][0], a1, b0); ffma2(acc2[1][1], a1, b1);
        ffma2(acc2[1][2], a1, b2); ffma2(acc2[1][3], a1, b3);
    }
    float* C = g_Lqk + (size_t)h * NN * NN;
#pragma unroll
    for (int u = 0; u < 2; ++u)
#pragma unroll
        for (int v = 0; v < 4; ++v) {
            float lo, hi;
            upk2(acc2[u][v], lo, hi);
            C[(size_t)(mb * 64 + ty * 4 + u * 2    ) * NN + nb * 64 + tx * 4 + v] = lo;
            C[(size_t)(mb * 64 + ty * 4 + u * 2 + 1) * NN + nb * 64 + tx * 4 + v] = hi;
        }
}

// ======== fused bias + logits + softmax + o1: ONE query row per block ========
// Phase A: bias = Wb @ z (reads z slab for row i -> lands in L2)
// softmax -> probs into smem `part` (+ g_A for o23)
// Phase B: o1 = probs @ z (z re-read, L2-hot)
__global__ __launch_bounds__(256, 2) void bias_softmax_kernel(const float* __restrict__ Z,
                                                              const float* __restrict__ Wb) {
    __shared__ ull   W2s[CZd * Hd];        // 12288 B
    __shared__ ull   part[Hd * 256];       // 24576 B: phase-A partials, then probs
    __shared__ float redM[Hd][4];
    __shared__ float redS[Hd][4];
    __shared__ float qns[Hd];

    const int tid = threadIdx.x;
    const int i = blockIdx.x;
    const int j4 = tid & 127;
    const int ch = tid >> 7;
    const int warp = tid >> 5;
    const int warpIn = warp;               // 0..3 for ch==0
    const int lane = tid & 31;
    const float w_l = 0.5773502691896258f;

    for (int e = tid; e < CZd * Hd; e += 256) {
        int c = e / 12, h = e % 12;
        float w = Wb[h * CZd + c];
        W2s[e] = pk2(w, w);
    }
    if (tid < 12) qns[tid] = g_qn[tid * NN + i];
    __syncthreads();

    ull acc[Hd][2];
#pragma unroll
    for (int h = 0; h < Hd; ++h) { acc[h][0] = 0ull; acc[h][1] = 0ull; }

    // ---- Phase A: bias partial over this thread's 64 c's ----
    const float4* z4 = (const float4*)Z + (size_t)i * 128 + j4;
    const int c0 = ch * 64;
    for (int cb = 0; cb < 64; cb += 8) {
        float4 zv[8];
#pragma unroll
        for (int u = 0; u < 8; ++u)
            zv[u] = __ldg(&z4[(size_t)(c0 + cb + u) * 65536]);
#pragma unroll
        for (int u = 0; u < 8; ++u) {
            ull zx = pk2(zv[u].x, zv[u].y), zy = pk2(zv[u].z, zv[u].w);
#pragma unroll
            for (int h = 0; h < Hd; ++h) {
                ull w2 = W2s[(c0 + cb + u) * 12 + h];
                ffma2(acc[h][0], w2, zx);
                ffma2(acc[h][1], w2, zy);
            }
        }
    }

    if (ch == 1) {
#pragma unroll
        for (int h = 0; h < Hd; ++h) {
            part[h * 256 + j4]       = acc[h][0];
            part[h * 256 + 128 + j4] = acc[h][1];
        }
    }
    __syncthreads();

    if (ch == 0) {
#pragma unroll
        for (int h = 0; h < Hd; ++h) {
            float a0, a1, b0, b1;
            upk2(acc[h][0], a0, a1);
            upk2(part[h * 256 + j4], b0, b1);
            float c0f = a0 + b0, c1f = a1 + b1;
            upk2(acc[h][1], a0, a1);
            upk2(part[h * 256 + 128 + j4], b0, b1);
            float c2f = a0 + b0, c3f = a1 + b1;

            float4 qk = __ldg((const float4*)g_Lqk + (size_t)h * 65536 + (size_t)i * 128 + j4);
            float4 kn = __ldg((const float4*)g_kn + h * 128 + j4);
            float qn = qns[h];
            c0f = w_l * (c0f + qk.x - qn - kn.x);
            c1f = w_l * (c1f + qk.y - qn - kn.y);
            c2f = w_l * (c2f + qk.z - qn - kn.z);
            c3f = w_l * (c3f + qk.w - qn - kn.w);
            acc[h][0] = pk2(c0f, c1f);
            acc[h][1] = pk2(c2f, c3f);
            float m = fmaxf(fmaxf(c0f, c1f), fmaxf(c2f, c3f));
#pragma unroll
            for (int o = 16; o; o >>= 1) m = fmaxf(m, __shfl_xor_sync(0xffffffffu, m, o));
            if (lane == 0) redM[h][warpIn] = m;
        }
    }
    __syncthreads();

    if (ch == 0) {
#pragma unroll
        for (int h = 0; h < Hd; ++h) {
            const float* r = redM[h];
            float m = fmaxf(fmaxf(r[0], r[1]), fmaxf(r[2], r[3]));
            float a0, a1, a2, a3;
            upk2(acc[h][0], a0, a1);
            upk2(acc[h][1], a2, a3);
            a0 = __expf(a0 - m); a1 = __expf(a1 - m);
            a2 = __expf(a2 - m); a3 = __expf(a3 - m);
            acc[h][0] = pk2(a0, a1);
            acc[h][1] = pk2(a2, a3);
            float s = (a0 + a1) + (a2 + a3);
#pragma unroll
            for (int o = 16; o; o >>= 1) s += __shfl_xor_sync(0xffffffffu, s, o);
            if (lane == 0) redS[h][warpIn] = s;
        }
    }
    __syncthreads();

    // normalize: write probs to g_A (for o23) AND into `part` (for phase B)
    if (ch == 0) {
        float4* A4 = (float4*)g_A;
        ulonglong2* P2w = (ulonglong2*)part;
#pragma unroll
        for (int h = 0; h < Hd; ++h) {
            const float* r = redS[h];
            float inv = 1.f / ((r[0] + r[1]) + (r[2] + r[3]));
            float a0, a1, a2, a3;
            upk2(acc[h][0], a0, a1);
            upk2(acc[h][1], a2, a3);
            a0 *= inv; a1 *= inv; a2 *= inv; a3 *= inv;
            float4 p;
            p.x = a0; p.y = a1; p.z = a2; p.w = a3;
            A4[(size_t)i * 1536 + h * 128 + j4] = p;
            ulonglong2 pp;
            pp.x = pk2(a0, a1);
            pp.y = pk2(a2, a3);
            P2w[h * 128 + j4] = pp;
        }
    }
    __syncthreads();

    // ---- Phase B: o1[c,h] = sum_j P[h,j] z[c,i,j] (z L2-hot) ----
    const ulonglong2* Ps2 = (const ulonglong2*)part;
#pragma unroll 1
    for (int cp = 0; cp < 8; ++cp) {
        const int c = cp * 16 + warp * 2;
        const ulonglong2* zc0 = (const ulonglong2*)(Z + ((size_t)c * NN + i) * NN);
        const ulonglong2* zc1 = (const ulonglong2*)(Z + ((size_t)(c + 1) * NN + i) * NN);
        ulonglong2 z0[4], z1[4];
#pragma unroll
        for (int q = 0; q < 4; ++q) {
            z0[q] = __ldg(&zc0[lane + 32 * q]);
            z1[q] = __ldg(&zc1[lane + 32 * q]);
        }
#pragma unroll
        for (int h = 0; h < Hd; ++h) { acc[h][0] = 0ull; acc[h][1] = 0ull; }
#pragma unroll
        for (int q = 0; q < 4; ++q) {
#pragma unroll
            for (int h = 0; h < Hd; ++h) {
                ulonglong2 pp = Ps2[h * 128 + lane + 32 * q];
                ffma2(acc[h][0], pp.x, z0[q].x);
                ffma2(acc[h][0], pp.y, z0[q].y);
                ffma2(acc[h][1], pp.x, z1[q].x);
                ffma2(acc[h][1], pp.y, z1[q].y);
            }
        }
#pragma unroll
        for (int h = 0; h < Hd; ++h) {
#pragma unroll
            for (int cc = 0; cc < 2; ++cc) {
                float lo, hi;
                upk2(acc[h][cc], lo, hi);
                float s = lo + hi;
#pragma unroll
                for (int o = 16; o; o >>= 1) s += __shfl_xor_sync(0xffffffffu, s, o);
                if (lane == 0) g_cat[(size_t)((c + cc) * Hd + h) * NN + i] = s;
            }
        }
    }
}

// ======== o2/o3 as per-head GEMM: O[48 r, 512 i] = V[48, 512 j] @ A_h[512 i, 512 j]^T ========
__global__ __launch_bounds__(256) void o23_gemm() {
    __shared__ float Vs[16][48];
    __shared__ float As[16][64];
    const int it = blockIdx.x, h = blockIdx.y;
    const int tid = threadIdx.x;
    const int tx = tid & 15, ty = tid >> 4;

    float acc[3][4];
#pragma unroll
    for (int u = 0; u < 3; ++u)
#pragma unroll
        for (int v = 0; v < 4; ++v) acc[u][v] = 0.f;

    const float* Vh = g_V + (size_t)h * 48 * NN;

    for (int kk = 0; kk < NN; kk += 16) {
#pragma unroll
        for (int l = 0; l < 3; ++l) {
            int e = tid + l * 256;
            int m = e >> 4, k = e & 15;
            Vs[k][m] = Vh[(size_t)m * NN + kk + k];
        }
#pragma unroll
        for (int l = 0; l < 4; ++l) {
            int e = tid + l * 256;
            int n = e >> 4, k = e & 15;
            As[k][n] = g_A[(size_t)(it * 64 + n) * (Hd * NN) + h * NN + kk + k];
        }
        __syncthreads();
#pragma unroll
        for (int k = 0; k < 16; ++k) {
            float a0 = Vs[k][ty * 3], a1 = Vs[k][ty * 3 + 1], a2 = Vs[k][ty * 3 + 2];
            float4 b = *(const float4*)&As[k][tx * 4];
            acc[0][0] += a0 * b.x; acc[0][1] += a0 * b.y; acc[0][2] += a0 * b.z; acc[0][3] += a0 * b.w;
            acc[1][0] += a1 * b.x; acc[1][1] += a1 * b.y; acc[1][2] += a1 * b.z; acc[1][3] += a1 * b.w;
            acc[2][0] += a2 * b.x; acc[2][1] += a2 * b.y; acc[2][2] += a2 * b.z; acc[2][3] += a2 * b.w;
        }
        __syncthreads();
    }

#pragma unroll
    for (int u = 0; u < 3; ++u) {
        int m = ty * 3 + u;
        if (m >= 40) continue;
#pragma unroll
        for (int v = 0; v < 4; ++v) {
            int i = it * 64 + tx * 4 + v;
            if (m < 16)
                g_cat[(size_t)(1536 + m * Hd + h) * NN + i] = acc[u][v];
            else {
                int d = m - 16;
                int rr = (d >> 3) * 96 + h * 8 + (d & 7);
                g_o3g[(size_t)rr * NN + i] = acc[u][v];
            }
        }
    }
}

// ---------------- o3 inverse transform + norm (warp per i) ----------------
__global__ void o3fix2(const float* __restrict__ t_r, const float* __restrict__ t_t) {
    int warp = threadIdx.x >> 5, lane = threadIdx.x & 31;
    int i = blockIdx.x * 8 + warp;
    float R[9], T[3];
#pragma unroll
    for (int r = 0; r < 9; ++r) R[r] = t_r[i * 9 + r];
#pragma unroll
    for (int c = 0; c < 3; ++c) T[c] = t_t[i * 3 + c];

    float nrm = 0.f;
    for (int hp = lane; hp < 96; hp += 32) {
        float a0 = g_o3g[(size_t)(0 * 96 + hp) * NN + i] - T[0];
        float a1 = g_o3g[(size_t)(1 * 96 + hp) * NN + i] - T[1];
        float a2 = g_o3g[(size_t)(2 * 96 + hp) * NN + i] - T[2];
#pragma unroll
        for (int co = 0; co < 3; ++co) {
            float v = R[co] * a0 + R[3 + co] * a1 + R[6 + co] * a2;
            g_cat[(size_t)(1728 + co * 96 + hp) * NN + i] = v;
            nrm += v * v;
        }
    }
#pragma unroll
    for (int o = 16; o; o >>= 1) nrm += __shfl_xor_sync(0xffffffffu, nrm, o);
    if (lane == 0) g_cat[(size_t)2016 * NN + i] = sqrtf(nrm);
}

// ---------------- final GEMM: 64x64 tiles, split-K (r10 proven) ----------------
__global__ __launch_bounds__(256) void gemm64(const float* __restrict__ A,
                                              const float* __restrict__ B,
                                              float* __restrict__ C,
                                              int M, int Nc, int K) {
    int nb = blockIdx.x, mb = blockIdx.y, zb = blockIdx.z;
    int Kc = (K + gridDim.z - 1) / gridDim.z;
    int k0 = zb * Kc;
    int kend = min(K, k0 + Kc);

    __shared__ float As[16][64];
    __shared__ ull   Bs2[16][64];

    int tid = threadIdx.x;
    int ty = tid >> 4, tx = tid & 15;
    ull acc2[2][4];
#pragma unroll
    for (int u = 0; u < 2; ++u)
#pragma unroll
        for (int v = 0; v < 4; ++v) acc2[u][v] = 0ull;

    for (int kk = k0; kk < kend; kk += 16) {
#pragma unroll
        for (int l = 0; l < 4; ++l) {
            int e = tid + l * 256;
            int m = e >> 4, k = e & 15;
            As[k][m] = (kk + k < kend) ? A[(size_t)(mb * 64 + m) * K + kk + k] : 0.f;
        }
#pragma unroll
        for (int l = 0; l < 4; ++l) {
            int e = tid + l * 256;
            int k = e >> 6, n = e & 63;
            float v = (kk + k < kend) ? B[(size_t)(kk + k) * Nc + nb * 64 + n] : 0.f;
            Bs2[k][n] = pk2(v, v);
        }
        __syncthreads();
#pragma unroll
        for (int k = 0; k < 16; ++k) {
            const ull* a2 = (const ull*)&As[k][ty * 4];
            ull a0 = a2[0], a1 = a2[1];
            ull b0 = Bs2[k][tx * 4], b1 = Bs2[k][tx * 4 + 1];
            ull b2 = Bs2[k][tx * 4 + 2], b3 = Bs2[k][tx * 4 + 3];
            ffma2(acc2[0][0], a0, b0); ffma2(acc2[0][1], a0, b1);
            ffma2(acc2[0][2], a0, b2); ffma2(acc2[0][3], a0, b3);
            ffma2(acc2[1][0], a1, b0); ffma2(acc2[1][1], a1, b1);
            ffma2(acc2[1][2], a1, b2); ffma2(acc2[1][3], a1, b3);
        }
        __syncthreads();
    }
    float* Cz = C + (size_t)zb * M * Nc;
#pragma unroll
    for (int u = 0; u < 2; ++u)
#pragma unroll
        for (int v = 0; v < 4; ++v) {
            float lo, hi;
            upk2(acc2[u][v], lo, hi);
            Cz[(size_t)(mb * 64 + ty * 4 + u * 2    ) * Nc + nb * 64 + tx * 4 + v] = lo;
            Cz[(size_t)(mb * 64 + ty * 4 + u * 2 + 1) * Nc + nb * 64 + tx * 4 + v] = hi;
        }
}

// ---------------- final reduce ----------------
__global__ void reduce_out(const float* __restrict__ bs, float* __restrict__ out) {
    int idx = blockIdx.x * 256 + threadIdx.x;
    if (idx >= CSd * NN) return;
    int o = idx >> 9;
    float v = bs[o];
#pragma unroll
    for (int zk = 0; zk < KSPLIT; ++zk) v += g_part[(size_t)zk * CSd * NN + idx];
    out[idx] = v;
}

// ---------------- launcher (serial) ----------------
extern "C" void kernel_launch(void* const* d_in, const int* in_sizes, int n_in,
                              void* d_out, int out_size) {
    const float* s    = (const float*)d_in[0];
    const float* z    = (const float*)d_in[1];
    const float* t_r  = (const float*)d_in[2];
    const float* t_t  = (const float*)d_in[3];
    const float* Wq   = (const float*)d_in[4];
    const float* Wk   = (const float*)d_in[5];
    const float* Wv   = (const float*)d_in[6];
    const float* Wqp  = (const float*)d_in[7];
    const float* Wkp  = (const float*)d_in[8];
    const float* Wvp  = (const float*)d_in[9];
    const float* Wb   = (const float*)d_in[10];
    const float* gam  = (const float*)d_in[11];
    const float* Ws   = (const float*)d_in[12];
    const float* bs   = (const float*)d_in[13];
    float* out = (float*)d_out;

    float *pCat, *pPart;
    cudaGetSymbolAddress((void**)&pCat,  g_cat);
    cudaGetSymbolAddress((void**)&pPart, g_part);

    proj_gemm<<<dim3(NN / 64, MPROJ / 64), 256>>>(s, Wq, Wk, Wv, Wqp, Wkp, Wvp);
    prep_kernel<<<Hd * NN / 128, 128>>>(t_r, t_t, gam);
    qk_gemm<<<dim3(NN / 64, NN / 64, Hd), 256>>>();
    bias_softmax_kernel<<<NN, 256>>>(z, Wb);
    o23_gemm<<<dim3(8, Hd), 256>>>();
    o3fix2<<<NN / 8, 256>>>(t_r, t_t);
    gemm64<<<dim3(NN / 64, CSd / 64, KSPLIT), 256>>>(Ws, pCat, pPart, CSd, NN, CATd);
    reduce_out<<<(CSd * NN + 255) / 256, 256>>>(bs, out);
}

// round 13
// speedup vs baseline: 1.1650x; 1.0062x over previous
#include <cuda_runtime.h>
#include <math.h>

#define NN   512
#define CSd  384
#define CZd  128
#define Hd   12
#define Cd   16
#define PQd  4
#define PVd  8
#define DE   28
#define CATd 2017
#define MPROJ 1152
#define KSPLIT 16

typedef unsigned long long ull;

// ---------------- packed f32x2 helpers ----------------
__device__ __forceinline__ void ffma2(ull& acc, ull a, ull b) {
    asm("fma.rn.f32x2 %0, %1, %2, %0;" : "+l"(acc) : "l"(a), "l"(b));
}
__device__ __forceinline__ ull pk2(float x, float y) {
    ull r; asm("mov.b64 %0, {%1,%2};" : "=l"(r) : "f"(x), "f"(y)); return r;
}
__device__ __forceinline__ void upk2(ull v, float& x, float& y) {
    asm("mov.b64 {%0,%1}, %2;" : "=f"(x), "=f"(y) : "l"(v));
}

// ---------------- device scratch ----------------
__device__ float g_P[MPROJ * NN];
__device__ float g_qe[Hd * DE * NN];
__device__ float g_ke[Hd * DE * NN];
__device__ float g_qn[Hd * NN];
__device__ float g_kn[Hd * NN];
__device__ float g_V[Hd * 48 * NN];
__device__ float g_Lqk[Hd * NN * NN];
__device__ float g_A[NN * Hd * NN];
__device__ float g_o3g[288 * NN];
__device__ float g_cat[CATd * NN];
__device__ float g_part[KSPLIT * CSd * NN];

// ---------------- projection GEMM with fused weight concat ----------------
__global__ __launch_bounds__(256) void proj_gemm(const float* __restrict__ s,
                                                 const float* __restrict__ Wq,
                                                 const float* __restrict__ Wk,
                                                 const float* __restrict__ Wv,
                                                 const float* __restrict__ Wqp,
                                                 const float* __restrict__ Wkp,
                                                 const float* __restrict__ Wvp) {
    __shared__ float As[16][64];
    __shared__ ull   Bs2[16][64];

    const int nb = blockIdx.x, mb = blockIdx.y;
    const int tid = threadIdx.x;
    const int ty = tid >> 4, tx = tid & 15;

    const float* rowp[4];
#pragma unroll
    for (int l = 0; l < 4; ++l) {
        int e = tid + l * 256;
        int r = mb * 64 + (e >> 4);
        const float* p;
        if      (r < 192) p = Wq  + (size_t)r * CSd;
        else if (r < 384) p = Wk  + (size_t)(r - 192) * CSd;
        else if (r < 576) p = Wv  + (size_t)(r - 384) * CSd;
        else if (r < 720) p = Wqp + (size_t)(r - 576) * CSd;
        else if (r < 864) p = Wkp + (size_t)(r - 720) * CSd;
        else              p = Wvp + (size_t)(r - 864) * CSd;
        rowp[l] = p;
    }

    ull acc2[2][4];
#pragma unroll
    for (int u = 0; u < 2; ++u)
#pragma unroll
        for (int v = 0; v < 4; ++v) acc2[u][v] = 0ull;

    for (int kk = 0; kk < CSd; kk += 16) {
#pragma unroll
        for (int l = 0; l < 4; ++l) {
            int e = tid + l * 256;
            As[e & 15][e >> 4] = rowp[l][kk + (e & 15)];
        }
#pragma unroll
        for (int l = 0; l < 4; ++l) {
            int e = tid + l * 256;
            int k = e >> 6, n = e & 63;
            float v = s[(size_t)(kk + k) * NN + nb * 64 + n];
            Bs2[k][n] = pk2(v, v);
        }
        __syncthreads();
#pragma unroll
        for (int k = 0; k < 16; ++k) {
            const ull* a2 = (const ull*)&As[k][ty * 4];
            ull a0 = a2[0], a1 = a2[1];
            ull b0 = Bs2[k][tx * 4], b1 = Bs2[k][tx * 4 + 1];
            ull b2 = Bs2[k][tx * 4 + 2], b3 = Bs2[k][tx * 4 + 3];
            ffma2(acc2[0][0], a0, b0); ffma2(acc2[0][1], a0, b1);
            ffma2(acc2[0][2], a0, b2); ffma2(acc2[0][3], a0, b3);
            ffma2(acc2[1][0], a1, b0); ffma2(acc2[1][1], a1, b1);
            ffma2(acc2[1][2], a1, b2); ffma2(acc2[1][3], a1, b3);
        }
        __syncthreads();
    }
#pragma unroll
    for (int u = 0; u < 2; ++u)
#pragma unroll
        for (int v = 0; v < 4; ++v) {
            float lo, hi;
            upk2(acc2[u][v], lo, hi);
            g_P[(size_t)(mb * 64 + ty * 4 + u * 2    ) * NN + nb * 64 + tx * 4 + v] = lo;
            g_P[(size_t)(mb * 64 + ty * 4 + u * 2 + 1) * NN + nb * 64 + tx * 4 + v] = hi;
        }
}

// ---------------- prep ----------------
__global__ __launch_bounds__(128) void prep_kernel(const float* __restrict__ t_r,
                                                   const float* __restrict__ t_t,
                                                   const float* __restrict__ gamma) {
    int idx = blockIdx.x * 128 + threadIdx.x;
    int h = idx >> 9, i = idx & 511;
    const float w_c = 0.23570226039551584f;
    float R[9], T[3];
#pragma unroll
    for (int r = 0; r < 9; ++r) R[r] = t_r[i * 9 + r];
#pragma unroll
    for (int c = 0; c < 3; ++c) T[c] = t_t[i * 3 + c];

    float x = gamma[h];
    float sp = (x > 20.f) ? x : log1pf(expf(x));
    float g = sp * w_c * 0.5f;

#pragma unroll
    for (int c = 0; c < Cd; ++c) {
        g_qe[(h * DE + c) * NN + i] = g_P[(      c * Hd + h) * NN + i] * 0.25f;
        g_ke[(h * DE + c) * NN + i] = g_P[(192 + c * Hd + h) * NN + i];
    }
    float qn = 0.f, kn = 0.f;
#pragma unroll
    for (int p = 0; p < PQd; ++p) {
        float q0 = g_P[(576 +  0 + h * 4 + p) * NN + i];
        float q1 = g_P[(576 + 48 + h * 4 + p) * NN + i];
        float q2 = g_P[(576 + 96 + h * 4 + p) * NN + i];
        float k0 = g_P[(720 +  0 + h * 4 + p) * NN + i];
        float k1 = g_P[(720 + 48 + h * 4 + p) * NN + i];
        float k2 = g_P[(720 + 96 + h * 4 + p) * NN + i];
#pragma unroll
        for (int co = 0; co < 3; ++co) {
            float qg = R[co * 3] * q0 + R[co * 3 + 1] * q1 + R[co * 3 + 2] * q2 + T[co];
            float kg = R[co * 3] * k0 + R[co * 3 + 1] * k1 + R[co * 3 + 2] * k2 + T[co];
            g_qe[(h * DE + 16 + co * 4 + p) * NN + i] = 2.f * g * qg;
            g_ke[(h * DE + 16 + co * 4 + p) * NN + i] = kg;
            qn += qg * qg;
            kn += kg * kg;
        }
    }
    g_qn[h * NN + i] = g * qn;
    g_kn[h * NN + i] = g * kn;

#pragma unroll
    for (int c = 0; c < Cd; ++c)
        g_V[(size_t)(h * 48 + c) * NN + i] = g_P[(384 + c * Hd + h) * NN + i];

#pragma unroll
    for (int p = 0; p < PVd; ++p) {
        float v0 = g_P[(864 +   0 + h * 8 + p) * NN + i];
        float v1 = g_P[(864 +  96 + h * 8 + p) * NN + i];
        float v2 = g_P[(864 + 192 + h * 8 + p) * NN + i];
#pragma unroll
        for (int co = 0; co < 3; ++co)
            g_V[(size_t)(h * 48 + 16 + co * 8 + p) * NN + i] =
                R[co * 3] * v0 + R[co * 3 + 1] * v1 + R[co * 3 + 2] * v2 + T[co];
    }
#pragma unroll
    for (int r = 40; r < 48; ++r)
        g_V[(size_t)(h * 48 + r) * NN + i] = 0.f;
}

// ---------------- qk batched GEMM v2: 64m x 128n tiles ----------------
__global__ __launch_bounds__(256) void qk_gemm() {
    __shared__ float As[DE][64];
    __shared__ ull   Bs2[DE][128];
    const int h = blockIdx.z, mb = blockIdx.y, nb = blockIdx.x;
    const float* Aq = g_qe + (size_t)h * DE * NN;
    const float* Bk = g_ke + (size_t)h * DE * NN;
    const int tid = threadIdx.x;
    const int tx = tid & 15, ty = tid >> 4;

#pragma unroll
    for (int l = 0; l < 7; ++l) {
        int e = tid + l * 256, k = e >> 6, m = e & 63;
        As[k][m] = Aq[k * NN + mb * 64 + m];
    }
#pragma unroll
    for (int l = 0; l < 14; ++l) {
        int e = tid + l * 256, k = e >> 7, n = e & 127;
        float v = Bk[k * NN + nb * 128 + n];
        Bs2[k][n] = pk2(v, v);
    }
    __syncthreads();

    ull acc2[2][8];
#pragma unroll
    for (int u = 0; u < 2; ++u)
#pragma unroll
        for (int v = 0; v < 8; ++v) acc2[u][v] = 0ull;

#pragma unroll
    for (int k = 0; k < DE; ++k) {
        const ull* a2 = (const ull*)&As[k][ty * 4];
        ull a0 = a2[0], a1 = a2[1];
        const ull* bp = &Bs2[k][tx * 8];
#pragma unroll
        for (int v = 0; v < 8; ++v) {
            ull bv = bp[v];
            ffma2(acc2[0][v], a0, bv);
            ffma2(acc2[1][v], a1, bv);
        }
    }
    float* C = g_Lqk + (size_t)h * NN * NN;
#pragma unroll
    for (int u = 0; u < 2; ++u)
#pragma unroll
        for (int v = 0; v < 8; ++v) {
            float lo, hi;
            upk2(acc2[u][v], lo, hi);
            C[(size_t)(mb * 64 + ty * 4 + u * 2    ) * NN + nb * 128 + tx * 8 + v] = lo;
            C[(size_t)(mb * 64 + ty * 4 + u * 2 + 1) * NN + nb * 128 + tx * 8 + v] = hi;
        }
}

// ======== fused bias + logits + softmax + o1: ONE query row per block ========
__global__ __launch_bounds__(256, 2) void bias_softmax_kernel(const float* __restrict__ Z,
                                                              const float* __restrict__ Wb) {
    __shared__ ull   W2s[CZd * Hd];
    __shared__ ull   part[Hd * 256];
    __shared__ float redM[Hd][4];
    __shared__ float redS[Hd][4];
    __shared__ float qns[Hd];

    const int tid = threadIdx.x;
    const int i = blockIdx.x;
    const int j4 = tid & 127;
    const int ch = tid >> 7;
    const int warp = tid >> 5;
    const int warpIn = warp;
    const int lane = tid & 31;
    const float w_l = 0.5773502691896258f;

    for (int e = tid; e < CZd * Hd; e += 256) {
        int c = e / 12, h = e % 12;
        float w = Wb[h * CZd + c];
        W2s[e] = pk2(w, w);
    }
    if (tid < 12) qns[tid] = g_qn[tid * NN + i];
    __syncthreads();

    ull acc[Hd][2];
#pragma unroll
    for (int h = 0; h < Hd; ++h) { acc[h][0] = 0ull; acc[h][1] = 0ull; }

    // ---- Phase A: bias partial over this thread's 64 c's ----
    const float4* z4 = (const float4*)Z + (size_t)i * 128 + j4;
    const int c0 = ch * 64;
    for (int cb = 0; cb < 64; cb += 8) {
        float4 zv[8];
#pragma unroll
        for (int u = 0; u < 8; ++u)
            zv[u] = __ldg(&z4[(size_t)(c0 + cb + u) * 65536]);
#pragma unroll
        for (int u = 0; u < 8; ++u) {
            ull zx = pk2(zv[u].x, zv[u].y), zy = pk2(zv[u].z, zv[u].w);
#pragma unroll
            for (int h = 0; h < Hd; ++h) {
                ull w2 = W2s[(c0 + cb + u) * 12 + h];
                ffma2(acc[h][0], w2, zx);
                ffma2(acc[h][1], w2, zy);
            }
        }
    }

    if (ch == 1) {
#pragma unroll
        for (int h = 0; h < Hd; ++h) {
            part[h * 256 + j4]       = acc[h][0];
            part[h * 256 + 128 + j4] = acc[h][1];
        }
    }
    __syncthreads();

    if (ch == 0) {
#pragma unroll
        for (int h = 0; h < Hd; ++h) {
            float a0, a1, b0, b1;
            upk2(acc[h][0], a0, a1);
            upk2(part[h * 256 + j4], b0, b1);
            float c0f = a0 + b0, c1f = a1 + b1;
            upk2(acc[h][1], a0, a1);
            upk2(part[h * 256 + 128 + j4], b0, b1);
            float c2f = a0 + b0, c3f = a1 + b1;

            float4 qk = __ldg((const float4*)g_Lqk + (size_t)h * 65536 + (size_t)i * 128 + j4);
            float4 kn = __ldg((const float4*)g_kn + h * 128 + j4);
            float qn = qns[h];
            c0f = w_l * (c0f + qk.x - qn - kn.x);
            c1f = w_l * (c1f + qk.y - qn - kn.y);
            c2f = w_l * (c2f + qk.z - qn - kn.z);
            c3f = w_l * (c3f + qk.w - qn - kn.w);
            acc[h][0] = pk2(c0f, c1f);
            acc[h][1] = pk2(c2f, c3f);
            float m = fmaxf(fmaxf(c0f, c1f), fmaxf(c2f, c3f));
#pragma unroll
            for (int o = 16; o; o >>= 1) m = fmaxf(m, __shfl_xor_sync(0xffffffffu, m, o));
            if (lane == 0) redM[h][warpIn] = m;
        }
    }
    __syncthreads();

    if (ch == 0) {
#pragma unroll
        for (int h = 0; h < Hd; ++h) {
            const float* r = redM[h];
            float m = fmaxf(fmaxf(r[0], r[1]), fmaxf(r[2], r[3]));
            float a0, a1, a2, a3;
            upk2(acc[h][0], a0, a1);
            upk2(acc[h][1], a2, a3);
            a0 = __expf(a0 - m); a1 = __expf(a1 - m);
            a2 = __expf(a2 - m); a3 = __expf(a3 - m);
            acc[h][0] = pk2(a0, a1);
            acc[h][1] = pk2(a2, a3);
            float s = (a0 + a1) + (a2 + a3);
#pragma unroll
            for (int o = 16; o; o >>= 1) s += __shfl_xor_sync(0xffffffffu, s, o);
            if (lane == 0) redS[h][warpIn] = s;
        }
    }
    __syncthreads();

    if (ch == 0) {
        float4* A4 = (float4*)g_A;
        ulonglong2* P2w = (ulonglong2*)part;
#pragma unroll
        for (int h = 0; h < Hd; ++h) {
            const float* r = redS[h];
            float inv = 1.f / ((r[0] + r[1]) + (r[2] + r[3]));
            float a0, a1, a2, a3;
            upk2(acc[h][0], a0, a1);
            upk2(acc[h][1], a2, a3);
            a0 *= inv; a1 *= inv; a2 *= inv; a3 *= inv;
            float4 p;
            p.x = a0; p.y = a1; p.z = a2; p.w = a3;
            A4[(size_t)i * 1536 + h * 128 + j4] = p;
            ulonglong2 pp;
            pp.x = pk2(a0, a1);
            pp.y = pk2(a2, a3);
            P2w[h * 128 + j4] = pp;
        }
    }
    __syncthreads();

    // ---- Phase B: o1, 4 c's per warp x 4-head sweeps (3 sweeps) ----
    const ulonglong2* Ps2 = (const ulonglong2*)part;
#pragma unroll 1
    for (int hh = 0; hh < 3; ++hh) {
        const int hbase = hh * 4;
#pragma unroll 1
        for (int cp = 0; cp < 4; ++cp) {
            const int c = cp * 32 + warp * 4;
            ull a6[4][4];
#pragma unroll
            for (int h = 0; h < 4; ++h)
#pragma unroll
                for (int cc = 0; cc < 4; ++cc) a6[h][cc] = 0ull;

#pragma unroll
            for (int q = 0; q < 4; ++q) {
                int jp = lane + 32 * q;
                ulonglong2 za = __ldg((const ulonglong2*)(Z + ((size_t)(c    ) * NN + i) * NN) + jp);
                ulonglong2 zb = __ldg((const ulonglong2*)(Z + ((size_t)(c + 1) * NN + i) * NN) + jp);
                ulonglong2 zc = __ldg((const ulonglong2*)(Z + ((size_t)(c + 2) * NN + i) * NN) + jp);
                ulonglong2 zd = __ldg((const ulonglong2*)(Z + ((size_t)(c + 3) * NN + i) * NN) + jp);
#pragma unroll
                for (int h = 0; h < 4; ++h) {
                    ulonglong2 pp = Ps2[(hbase + h) * 128 + jp];
                    ffma2(a6[h][0], pp.x, za.x); ffma2(a6[h][0], pp.y, za.y);
                    ffma2(a6[h][1], pp.x, zb.x); ffma2(a6[h][1], pp.y, zb.y);
                    ffma2(a6[h][2], pp.x, zc.x); ffma2(a6[h][2], pp.y, zc.y);
                    ffma2(a6[h][3], pp.x, zd.x); ffma2(a6[h][3], pp.y, zd.y);
                }
            }
#pragma unroll
            for (int h = 0; h < 4; ++h) {
#pragma unroll
                for (int cc = 0; cc < 4; ++cc) {
                    float lo, hi;
                    upk2(a6[h][cc], lo, hi);
                    float s = lo + hi;
#pragma unroll
                    for (int o = 16; o; o >>= 1) s += __shfl_xor_sync(0xffffffffu, s, o);
                    if (lane == 0) g_cat[(size_t)((c + cc) * Hd + hbase + h) * NN + i] = s;
                }
            }
        }
    }
}

// ======== o2/o3 per-head GEMM ========
__global__ __launch_bounds__(256) void o23_gemm() {
    __shared__ float Vs[16][48];
    __shared__ float As[16][64];
    const int it = blockIdx.x, h = blockIdx.y;
    const int tid = threadIdx.x;
    const int tx = tid & 15, ty = tid >> 4;

    float acc[3][4];
#pragma unroll
    for (int u = 0; u < 3; ++u)
#pragma unroll
        for (int v = 0; v < 4; ++v) acc[u][v] = 0.f;

    const float* Vh = g_V + (size_t)h * 48 * NN;

    for (int kk = 0; kk < NN; kk += 16) {
#pragma unroll
        for (int l = 0; l < 3; ++l) {
            int e = tid + l * 256;
            int m = e >> 4, k = e & 15;
            Vs[k][m] = Vh[(size_t)m * NN + kk + k];
        }
#pragma unroll
        for (int l = 0; l < 4; ++l) {
            int e = tid + l * 256;
            int n = e >> 4, k = e & 15;
            As[k][n] = g_A[(size_t)(it * 64 + n) * (Hd * NN) + h * NN + kk + k];
        }
        __syncthreads();
#pragma unroll
        for (int k = 0; k < 16; ++k) {
            float a0 = Vs[k][ty * 3], a1 = Vs[k][ty * 3 + 1], a2 = Vs[k][ty * 3 + 2];
            float4 b = *(const float4*)&As[k][tx * 4];
            acc[0][0] += a0 * b.x; acc[0][1] += a0 * b.y; acc[0][2] += a0 * b.z; acc[0][3] += a0 * b.w;
            acc[1][0] += a1 * b.x; acc[1][1] += a1 * b.y; acc[1][2] += a1 * b.z; acc[1][3] += a1 * b.w;
            acc[2][0] += a2 * b.x; acc[2][1] += a2 * b.y; acc[2][2] += a2 * b.z; acc[2][3] += a2 * b.w;
        }
        __syncthreads();
    }

#pragma unroll
    for (int u = 0; u < 3; ++u) {
        int m = ty * 3 + u;
        if (m >= 40) continue;
#pragma unroll
        for (int v = 0; v < 4; ++v) {
            int i = it * 64 + tx * 4 + v;
            if (m < 16)
                g_cat[(size_t)(1536 + m * Hd + h) * NN + i] = acc[u][v];
            else {
                int d = m - 16;
                int rr = (d >> 3) * 96 + h * 8 + (d & 7);
                g_o3g[(size_t)rr * NN + i] = acc[u][v];
            }
        }
    }
}

// ---------------- o3 inverse transform + norm ----------------
__global__ void o3fix2(const float* __restrict__ t_r, const float* __restrict__ t_t) {
    int warp = threadIdx.x >> 5, lane = threadIdx.x & 31;
    int i = blockIdx.x * 8 + warp;
    float R[9], T[3];
#pragma unroll
    for (int r = 0; r < 9; ++r) R[r] = t_r[i * 9 + r];
#pragma unroll
    for (int c = 0; c < 3; ++c) T[c] = t_t[i * 3 + c];

    float nrm = 0.f;
    for (int hp = lane; hp < 96; hp += 32) {
        float a0 = g_o3g[(size_t)(0 * 96 + hp) * NN + i] - T[0];
        float a1 = g_o3g[(size_t)(1 * 96 + hp) * NN + i] - T[1];
        float a2 = g_o3g[(size_t)(2 * 96 + hp) * NN + i] - T[2];
#pragma unroll
        for (int co = 0; co < 3; ++co) {
            float v = R[co] * a0 + R[3 + co] * a1 + R[6 + co] * a2;
            g_cat[(size_t)(1728 + co * 96 + hp) * NN + i] = v;
            nrm += v * v;
        }
    }
#pragma unroll
    for (int o = 16; o; o >>= 1) nrm += __shfl_xor_sync(0xffffffffu, nrm, o);
    if (lane == 0) g_cat[(size_t)2016 * NN + i] = sqrtf(nrm);
}

// ---------------- final GEMM: 64x64 tiles, split-K ----------------
__global__ __launch_bounds__(256) void gemm64(const float* __restrict__ A,
                                              const float* __restrict__ B,
                                              float* __restrict__ C,
                                              int M, int Nc, int K) {
    int nb = blockIdx.x, mb = blockIdx.y, zb = blockIdx.z;
    int Kc = (K + gridDim.z - 1) / gridDim.z;
    int k0 = zb * Kc;
    int kend = min(K, k0 + Kc);

    __shared__ float As[16][64];
    __shared__ ull   Bs2[16][64];

    int tid = threadIdx.x;
    int ty = tid >> 4, tx = tid & 15;
    ull acc2[2][4];
#pragma unroll
    for (int u = 0; u < 2; ++u)
#pragma unroll
        for (int v = 0; v < 4; ++v) acc2[u][v] = 0ull;

    for (int kk = k0; kk < kend; kk += 16) {
#pragma unroll
        for (int l = 0; l < 4; ++l) {
            int e = tid + l * 256;
            int m = e >> 4, k = e & 15;
            As[k][m] = (kk + k < kend) ? A[(size_t)(mb * 64 + m) * K + kk + k] : 0.f;
        }
#pragma unroll
        for (int l = 0; l < 4; ++l) {
            int e = tid + l * 256;
            int k = e >> 6, n = e & 63;
            float v = (kk + k < kend) ? B[(size_t)(kk + k) * Nc + nb * 64 + n] : 0.f;
            Bs2[k][n] = pk2(v, v);
        }
        __syncthreads();
#pragma unroll
        for (int k = 0; k < 16; ++k) {
            const ull* a2 = (const ull*)&As[k][ty * 4];
            ull a0 = a2[0], a1 = a2[1];
            ull b0 = Bs2[k][tx * 4], b1 = Bs2[k][tx * 4 + 1];
            ull b2 = Bs2[k][tx * 4 + 2], b3 = Bs2[k][tx * 4 + 3];
            ffma2(acc2[0][0], a0, b0); ffma2(acc2[0][1], a0, b1);
            ffma2(acc2[0][2], a0, b2); ffma2(acc2[0][3], a0, b3);
            ffma2(acc2[1][0], a1, b0); ffma2(acc2[1][1], a1, b1);
            ffma2(acc2[1][2], a1, b2); ffma2(acc2[1][3], a1, b3);
        }
        __syncthreads();
    }
    float* Cz = C + (size_t)zb * M * Nc;
#pragma unroll
    for (int u = 0; u < 2; ++u)
#pragma unroll
        for (int v = 0; v < 4; ++v) {
            float lo, hi;
            upk2(acc2[u][v], lo, hi);
            Cz[(size_t)(mb * 64 + ty * 4 + u * 2    ) * Nc + nb * 64 + tx * 4 + v] = lo;
            Cz[(size_t)(mb * 64 + ty * 4 + u * 2 + 1) * Nc + nb * 64 + tx * 4 + v] = hi;
        }
}

// ---------------- final reduce ----------------
__global__ void reduce_out(const float* __restrict__ bs, float* __restrict__ out) {
    int idx = blockIdx.x * 256 + threadIdx.x;
    if (idx >= CSd * NN) return;
    int o = idx >> 9;
    float v = bs[o];
#pragma unroll
    for (int zk = 0; zk < KSPLIT; ++zk) v += g_part[(size_t)zk * CSd * NN + idx];
    out[idx] = v;
}

// ---------------- launcher ----------------
extern "C" void kernel_launch(void* const* d_in, const int* in_sizes, int n_in,
                              void* d_out, int out_size) {
    const float* s    = (const float*)d_in[0];
    const float* z    = (const float*)d_in[1];
    const float* t_r  = (const float*)d_in[2];
    const float* t_t  = (const float*)d_in[3];
    const float* Wq   = (const float*)d_in[4];
    const float* Wk   = (const float*)d_in[5];
    const float* Wv   = (const float*)d_in[6];
    const float* Wqp  = (const float*)d_in[7];
    const float* Wkp  = (const float*)d_in[8];
    const float* Wvp  = (const float*)d_in[9];
    const float* Wb   = (const float*)d_in[10];
    const float* gam  = (const float*)d_in[11];
    const float* Ws   = (const float*)d_in[12];
    const float* bs   = (const float*)d_in[13];
    float* out = (float*)d_out;

    float *pCat, *pPart;
    cudaGetSymbolAddress((void**)&pCat,  g_cat);
    cudaGetSymbolAddress((void**)&pPart, g_part);

    proj_gemm<<<dim3(NN / 64, MPROJ / 64), 256>>>(s, Wq, Wk, Wv, Wqp, Wkp, Wvp);
    prep_kernel<<<Hd * NN / 128, 128>>>(t_r, t_t, gam);
    qk_gemm<<<dim3(NN / 128, NN / 64, Hd), 256>>>();
    bias_softmax_kernel<<<NN, 256>>>(z, Wb);
    o23_gemm<<<dim3(8, Hd), 256>>>();
    o3fix2<<<NN / 8, 256>>>(t_r, t_t);
    gemm64<<<dim3(NN / 64, CSd / 64, KSPLIT), 256>>>(Ws, pCat, pPart, CSd, NN, CATd);
    reduce_out<<<(CSd * NN + 255) / 256, 256>>>(bs, out);
}